// round 11
// baseline (speedup 1.0000x reference)
#include <cuda_runtime.h>
#include <stdint.h>

#define NN    8192
#define KSEL  64
#define NT    256
#define EPT4  8            // float4 elements per thread (NN / NT / 4)
#define CAP   512          // candidate capacity (mean ~134, sigma ~11.5 at th=2.40)
#define THF   2.40f
#define MARGIN_ULPS 8u
#define ONEBITS 0x3f800000u

// Bit-exact replica of XLA's EmitFastTanh (f32, with_fma=true variant).
__device__ __forceinline__ float xla_tanh(float x) {
    const float pc = 7.99881172180175781f;
    float xc = fminf(fmaxf(x, -pc), pc);
    float x2 = __fmul_rn(xc, xc);
    float num = -2.76076847742355e-16f;
    num = __fmaf_rn(x2, num, 2.00018790482477e-13f);
    num = __fmaf_rn(x2, num, -8.60467152213735e-11f);
    num = __fmaf_rn(x2, num, 5.12229709037114e-08f);
    num = __fmaf_rn(x2, num, 1.48572235717979e-05f);
    num = __fmaf_rn(x2, num, 6.37261928875436e-04f);
    num = __fmaf_rn(x2, num, 4.89352455891786e-03f);
    num = __fmul_rn(xc, num);
    float den = 1.19825839466702e-06f;
    den = __fmaf_rn(x2, den, 1.18534705686654e-04f);
    den = __fmaf_rn(x2, den, 2.26843463243900e-03f);
    den = __fmaf_rn(x2, den, 4.89352518554385e-03f);
    float r = __fdiv_rn(num, den);
    return (fabsf(x) < 0.0004f) ? x : r;
}

// packed: (key << 13) | (8191 - idx). Larger packed == better in top_k order.
__device__ __forceinline__ unsigned long long pack_ki(uint32_t key, uint32_t idx) {
    return ((unsigned long long)key << 13) | (8191u - idx);
}

__global__ __launch_bounds__(NT, 6) void topk_tanh_kernel(
    const float* __restrict__ A, float* __restrict__ out)
{
    __shared__ unsigned long long s_pack[CAP];  // raw (A_bits<<32|idx), then packed
    __shared__ float              s_val[CAP];   // signed adj value
    __shared__ uint32_t           s_hist[256];
    __shared__ uint32_t           s_eq[CAP];    // (idx<<9)|slot for boundary-bin ties
    __shared__ uint32_t           s_cnt, s_eqcnt, s_D, s_E;
    __shared__ unsigned long long s_P;

    const int t   = threadIdx.x;
    const int row = blockIdx.x;
    const float* rowA = A + (size_t)row * NN;
    const float4* rp = (const float4*)rowA;
    float4* op = (float4*)(out + (size_t)row * NN);
    float* orow = out + (size_t)row * NN;

    if (t == 0) s_cnt = 0;
    __syncthreads();

    // ---- Phase 1: stream row (evict-first), zero-fill out (streaming stores),
    //      build per-thread candidate bitmap. 2x interleave for MLP.
    const float4 z4 = make_float4(0.f, 0.f, 0.f, 0.f);
    uint32_t mask = 0u;
#pragma unroll
    for (int i = 0; i < EPT4; i += 2) {
        const int b4a = i * NT + t;
        const int b4b = (i + 1) * NT + t;
        float4 va = __ldcs(&rp[b4a]);
        float4 vb = __ldcs(&rp[b4b]);
        __stcs(&op[b4a], z4);
        __stcs(&op[b4b], z4);
        if (fabsf(va.x) > THF) mask |= (1u << (4 * i + 0));
        if (fabsf(va.y) > THF) mask |= (1u << (4 * i + 1));
        if (fabsf(va.z) > THF) mask |= (1u << (4 * i + 2));
        if (fabsf(va.w) > THF) mask |= (1u << (4 * i + 3));
        if (fabsf(vb.x) > THF) mask |= (1u << (4 * i + 4));
        if (fabsf(vb.y) > THF) mask |= (1u << (4 * i + 5));
        if (fabsf(vb.z) > THF) mask |= (1u << (4 * i + 6));
        if (fabsf(vb.w) > THF) mask |= (1u << (4 * i + 7));
    }
    // Deferred push (~0.5 candidates/thread); re-fetch hits L1/L2.
    while (mask) {
        int b = __ffs(mask) - 1;
        mask &= mask - 1u;
        uint32_t idx = (uint32_t)(((b >> 2) * NT + t) * 4 + (b & 3));
        uint32_t bits = __float_as_uint(__ldg(rowA + idx));
        uint32_t p = atomicAdd(&s_cnt, 1u);
        if (p < CAP) s_pack[p] = ((unsigned long long)bits << 32) | idx;
    }
    __syncthreads();
    uint32_t cnt = s_cnt;
    uint32_t tb = __float_as_uint(THF);

    // ---- Rare: count out of [K, CAP] -> bisect |A|-bit threshold ------------
    if (__builtin_expect(cnt < KSEL || cnt > CAP, 0)) {
        uint32_t lo = 0u, hi = 0x7f800000u;
        if (cnt < KSEL) hi = tb; else lo = tb;
        for (int iter = 0; iter < 34; iter++) {
            uint32_t tk = lo + ((hi - lo) >> 1);
            __syncthreads();
            if (t == 0) s_cnt = 0;
            __syncthreads();
            for (int j = t; j < NN; j += NT) {
                uint32_t b = __float_as_uint(rowA[j]);
                if ((b & 0x7fffffffu) > tk) {
                    uint32_t p = atomicAdd(&s_cnt, 1u);
                    if (p < CAP) s_pack[p] = ((unsigned long long)b << 32) | (uint32_t)j;
                }
            }
            __syncthreads();
            cnt = s_cnt;
            tb = tk;
            if (cnt >= KSEL && cnt <= CAP) break;
            if (cnt < KSEL) hi = tk; else lo = tk;
            if (hi - lo <= 1u) break;
        }
        if (cnt > CAP) cnt = CAP;
    }
    uint32_t c = cnt;

    // ---- Phase 2: exact tanh keys for candidates, in-place repack -----------
    for (uint32_t i = t; i < c; i += NT) {
        unsigned long long raw = s_pack[i];
        float a = __uint_as_float((uint32_t)(raw >> 32));
        uint32_t idx = (uint32_t)(raw & 0xffffffffu);
        float adj = xla_tanh(3.0f * a);
        uint32_t key = __float_as_uint(adj) & 0x7fffffffu;
        s_pack[i] = pack_ki(key, idx);
        s_val[i]  = adj;
    }
    __syncthreads();

    // ---- Phase 3: O(c) histogram select on d = bits(1.0) - key --------------
    const bool selAll = (c < KSEL);
    bool useRank = false;
    if (!selAll) {
        s_hist[t] = 0;
        __syncthreads();
        for (uint32_t i = t; i < c; i += NT) {
            uint32_t d = ONEBITS - (uint32_t)(s_pack[i] >> 13);
            atomicAdd(&s_hist[d > 255u ? 255u : d], 1u);
        }
        __syncthreads();
        if (t < 32) {
            uint32_t p = 0;
#pragma unroll
            for (int j = 0; j < 8; j++) p += s_hist[t * 8 + j];
            uint32_t inc = p;
#pragma unroll
            for (int d = 1; d < 32; d <<= 1) {
                uint32_t v = __shfl_up_sync(0xffffffffu, inc, d);
                if (t >= d) inc += v;
            }
            uint32_t exc = inc - p;
            if (exc < KSEL && inc >= KSEL) {       // exactly one lane
                uint32_t cum = exc;
                for (int j = 0; j < 8; j++) {
                    uint32_t h = s_hist[t * 8 + j];
                    if (cum + h >= KSEL) { s_D = (uint32_t)(t * 8 + j); s_E = KSEL - cum; break; }
                    cum += h;
                }
            }
        }
        __syncthreads();
        if (s_D == 255u) useRank = true;           // overflow bin ambiguous: cold
    }

    // ---- Cold: c^2 rank fallback when histogram can't resolve ---------------
    if (__builtin_expect(useRank, 0)) {
        for (uint32_t i = t; i < c; i += NT) {
            unsigned long long me = s_pack[i];
            uint32_t r = 0;
            for (uint32_t j = 0; j < c; j++) r += (s_pack[j] > me);
            if (r == KSEL - 1) s_P = me;
        }
        __syncthreads();
    }

    // ---- Safety guard: can any excluded element (|A| <= tb) reach Tkey? -----
    if (!selAll) {
        uint32_t Tkey = useRank ? (uint32_t)(s_P >> 13) : (ONEBITS - s_D);
        float tfl = __uint_as_float(tb);
        uint32_t keysafe = (__float_as_uint(xla_tanh(3.0f * tfl)) & 0x7fffffffu) + MARGIN_ULPS;
        if (__builtin_expect(Tkey <= keysafe, 0)) {
            unsigned long long Pcol = ((unsigned long long)Tkey) << 13;
            __syncthreads();
            if (t == 0) s_cnt = 0;
            __syncthreads();
            for (int j = t; j < NN; j += NT) {
                float adj = xla_tanh(3.0f * rowA[j]);
                uint32_t key = __float_as_uint(adj) & 0x7fffffffu;
                unsigned long long pk = pack_ki(key, (uint32_t)j);
                if (pk >= Pcol) {
                    uint32_t p = atomicAdd(&s_cnt, 1u);
                    if (p < CAP) { s_pack[p] = pk; s_val[p] = adj; }
                }
            }
            __syncthreads();
            uint32_t c2 = s_cnt; if (c2 > CAP) c2 = CAP;
            for (uint32_t i = t; i < c2; i += NT) {
                unsigned long long me = s_pack[i];
                uint32_t r = 0;
                for (uint32_t j = 0; j < c2; j++) r += (s_pack[j] > me);
                if (r == KSEL - 1) s_P = me;
            }
            __syncthreads();
            c = c2;
            useRank = true;
        }
    }

    // ---- Phase 4: scatter the exactly-K selected values ---------------------
    // __syncthreads orders the zero-fill stores before these same-address stores.
    if (selAll) {
        for (uint32_t i = t; i < c; i += NT) {
            uint32_t idx = 8191u - (uint32_t)(s_pack[i] & 8191u);
            orow[idx] = s_val[i];
        }
    } else if (useRank) {
        unsigned long long P = s_P;
        for (uint32_t i = t; i < c; i += NT) {
            unsigned long long pk = s_pack[i];
            if (pk >= P) {
                uint32_t idx = 8191u - (uint32_t)(pk & 8191u);
                orow[idx] = s_val[i];
            }
        }
    } else {
        if (t == 0) s_eqcnt = 0;
        __syncthreads();
        const uint32_t D = s_D, E = s_E;
        for (uint32_t i = t; i < c; i += NT) {
            unsigned long long pk = s_pack[i];
            uint32_t d = ONEBITS - (uint32_t)(pk >> 13);
            uint32_t idx = 8191u - (uint32_t)(pk & 8191u);
            if (d < D) {
                orow[idx] = s_val[i];                       // strictly above threshold
            } else if (d == D) {
                uint32_t q = atomicAdd(&s_eqcnt, 1u);
                s_eq[q] = (idx << 9) | i;                   // idx:13b | slot:9b
            }
        }
        __syncthreads();
        const uint32_t Q = s_eqcnt;
        for (uint32_t m = t; m < Q; m += NT) {              // Q^2 ~ 4K: cheap
            uint32_t me = s_eq[m];
            uint32_t r = 0;
            for (uint32_t j = 0; j < Q; j++) r += (s_eq[j] < me);
            if (r < E) {                                    // E lowest indices win
                uint32_t i = me & 511u;
                orow[me >> 9] = s_val[i];
            }
        }
    }
}

extern "C" void kernel_launch(void* const* d_in, const int* in_sizes, int n_in,
                              void* d_out, int out_size)
{
    const float* A = nullptr;
    for (int i = 0; i < n_in; i++)
        if (in_sizes[i] == NN * NN) A = (const float*)d_in[i];
    float* out = (float*)d_out;
    topk_tanh_kernel<<<NN, NT>>>(A, out);
}

// round 12
// speedup vs baseline: 1.3108x; 1.3108x over previous
#include <cuda_runtime.h>
#include <stdint.h>

#define NN    8192
#define KSEL  64
#define NT    256
#define EPT4  8            // float4 elements per thread (NN / NT / 4)
#define CAP   512          // candidate capacity (mean ~154, sigma ~12 at c=2.35)
#define MARGIN_ULPS 8u

// Bit-exact replica of XLA's EmitFastTanh (f32, with_fma=true variant).
__device__ __forceinline__ float xla_tanh(float x) {
    const float pc = 7.99881172180175781f;
    float xc = fminf(fmaxf(x, -pc), pc);
    float x2 = __fmul_rn(xc, xc);
    float num = -2.76076847742355e-16f;
    num = __fmaf_rn(x2, num, 2.00018790482477e-13f);
    num = __fmaf_rn(x2, num, -8.60467152213735e-11f);
    num = __fmaf_rn(x2, num, 5.12229709037114e-08f);
    num = __fmaf_rn(x2, num, 1.48572235717979e-05f);
    num = __fmaf_rn(x2, num, 6.37261928875436e-04f);
    num = __fmaf_rn(x2, num, 4.89352455891786e-03f);
    num = __fmul_rn(xc, num);
    float den = 1.19825839466702e-06f;
    den = __fmaf_rn(x2, den, 1.18534705686654e-04f);
    den = __fmaf_rn(x2, den, 2.26843463243900e-03f);
    den = __fmaf_rn(x2, den, 4.89352518554385e-03f);
    float r = __fdiv_rn(num, den);
    return (fabsf(x) < 0.0004f) ? x : r;
}

// packed: (key << 13) | (8191 - idx). Larger packed == better in top_k order
// (larger |adj| key, ties broken by lower index). Values unique (idx unique).
__device__ __forceinline__ unsigned long long pack_ki(uint32_t key, uint32_t idx) {
    return ((unsigned long long)key << 13) | (8191u - idx);
}

__global__ __launch_bounds__(NT, 6) void topk_tanh_kernel(
    const float* __restrict__ A, float* __restrict__ out)
{
    __shared__ unsigned long long s_pack[CAP];  // raw (A_bits<<32|idx), then packed
    __shared__ float              s_val[CAP];   // signed adj value
    __shared__ uint32_t           s_cnt;
    __shared__ unsigned long long s_P;

    const int t   = threadIdx.x;
    const int row = blockIdx.x;
    const float* rowA = A + (size_t)row * NN;
    const float4* rp = (const float4*)rowA;
    float4* op = (float4*)(out + (size_t)row * NN);

    if (t == 0) s_cnt = 0;
    __syncthreads();

    // ---- Phase 1: stream row: |A|-bit candidate filter + fused zero-fill ----
    uint32_t tb = __float_as_uint(2.35f);     // |A| threshold bits (abs-bit compare)
    const float4 z4 = make_float4(0.f, 0.f, 0.f, 0.f);
#pragma unroll
    for (int i = 0; i < EPT4; i++) {
        const int b4 = i * NT + t;
        float4 v = rp[b4];
        op[b4] = z4;                           // zero-fill (selection-independent)
        const uint32_t idx0 = (uint32_t)(b4 * 4);
        uint32_t b0 = __float_as_uint(v.x), b1 = __float_as_uint(v.y);
        uint32_t b2 = __float_as_uint(v.z), b3 = __float_as_uint(v.w);
        if ((b0 & 0x7fffffffu) > tb) { uint32_t p = atomicAdd(&s_cnt, 1u); if (p < CAP) s_pack[p] = ((unsigned long long)b0 << 32) | (idx0 + 0u); }
        if ((b1 & 0x7fffffffu) > tb) { uint32_t p = atomicAdd(&s_cnt, 1u); if (p < CAP) s_pack[p] = ((unsigned long long)b1 << 32) | (idx0 + 1u); }
        if ((b2 & 0x7fffffffu) > tb) { uint32_t p = atomicAdd(&s_cnt, 1u); if (p < CAP) s_pack[p] = ((unsigned long long)b2 << 32) | (idx0 + 2u); }
        if ((b3 & 0x7fffffffu) > tb) { uint32_t p = atomicAdd(&s_cnt, 1u); if (p < CAP) s_pack[p] = ((unsigned long long)b3 << 32) | (idx0 + 3u); }
    }
    __syncthreads();
    uint32_t cnt = s_cnt;

    // ---- Rare: count out of [K, CAP] -> bisect |A|-bit threshold (global re-read)
    if (__builtin_expect(cnt < KSEL || cnt > CAP, 0)) {
        uint32_t lo = 0u, hi = 0x7f800000u;
        if (cnt < KSEL) hi = tb; else lo = tb;
        for (int iter = 0; iter < 34; iter++) {
            uint32_t tk = lo + ((hi - lo) >> 1);
            __syncthreads();
            if (t == 0) s_cnt = 0;
            __syncthreads();
            for (int j = t; j < NN; j += NT) {
                uint32_t b = __float_as_uint(rowA[j]);
                if ((b & 0x7fffffffu) > tk) {
                    uint32_t p = atomicAdd(&s_cnt, 1u);
                    if (p < CAP) s_pack[p] = ((unsigned long long)b << 32) | (uint32_t)j;
                }
            }
            __syncthreads();
            cnt = s_cnt;
            tb = tk;
            if (cnt >= KSEL && cnt <= CAP) break;
            if (cnt < KSEL) hi = tk; else lo = tk;
            if (hi - lo <= 1u) break;
        }
        if (cnt > CAP) cnt = CAP;   // degenerate massive-tie guard
    }
    const uint32_t c = cnt;

    // ---- Phase 2: exact tanh keys for candidates, in-place repack -----------
    for (uint32_t i = t; i < c; i += NT) {
        unsigned long long raw = s_pack[i];
        float a = __uint_as_float((uint32_t)(raw >> 32));
        uint32_t idx = (uint32_t)(raw & 0xffffffffu);
        float adj = xla_tanh(3.0f * a);
        uint32_t key = __float_as_uint(adj) & 0x7fffffffu;
        s_pack[i] = pack_ki(key, idx);
        s_val[i]  = adj;
    }
    __syncthreads();

    // ---- Phase 3: rank-select 64th largest packed among candidates ----------
    if (c >= KSEL) {
        for (uint32_t i = t; i < c; i += NT) {
            unsigned long long me = s_pack[i];
            uint32_t r = 0;
            for (uint32_t j = 0; j < c; j++) r += (s_pack[j] > me);
            if (r == KSEL - 1) s_P = me;
        }
    } else if (t == 0) {
        s_P = 0ull;   // < K nonzero |A|: select all candidates (rest exact 0)
    }
    __syncthreads();
    unsigned long long P = s_P;
    uint32_t selCnt = c;

    // ---- Safety check: can any excluded element (|A| <= tb) reach P? --------
    // Excluded keys <= key(xla_tanh(3*tb)) + small slop (approx is ~monotone to
    // a couple ulps). If the provisional threshold clears that with margin, the
    // fast path is exact. Otherwise: exact full-row rescan for packed >= P.
    {
        float tfl = __uint_as_float(tb);
        uint32_t keysafe = (__float_as_uint(xla_tanh(3.0f * tfl)) & 0x7fffffffu) + MARGIN_ULPS;
        uint32_t Tkey = (uint32_t)(P >> 13);
        if (__builtin_expect(c >= KSEL && Tkey <= keysafe, 0)) {
            __syncthreads();
            if (t == 0) s_cnt = 0;
            __syncthreads();
            for (int j = t; j < NN; j += NT) {
                float adj = xla_tanh(3.0f * rowA[j]);
                uint32_t key = __float_as_uint(adj) & 0x7fffffffu;
                unsigned long long pk = pack_ki(key, (uint32_t)j);
                if (pk >= P) {
                    uint32_t p = atomicAdd(&s_cnt, 1u);
                    if (p < CAP) { s_pack[p] = pk; s_val[p] = adj; }
                }
            }
            __syncthreads();
            uint32_t c2 = s_cnt; if (c2 > CAP) c2 = CAP;
            for (uint32_t i = t; i < c2; i += NT) {
                unsigned long long me = s_pack[i];
                uint32_t r = 0;
                for (uint32_t j = 0; j < c2; j++) r += (s_pack[j] > me);
                if (r == KSEL - 1) s_P = me;
            }
            __syncthreads();
            P = s_P;
            selCnt = c2;
        }
    }

    // ---- Phase 4: scatter the exactly-K selected values ---------------------
    // Zero-fill happened before the barriers above; __syncthreads orders the
    // same-address global stores within the CTA, so these stores win.
    for (uint32_t i = t; i < selCnt; i += NT) {
        unsigned long long pk = s_pack[i];
        if (pk >= P) {
            uint32_t idx = 8191u - (uint32_t)(pk & 8191u);
            out[(size_t)row * NN + idx] = s_val[i];
        }
    }
}

extern "C" void kernel_launch(void* const* d_in, const int* in_sizes, int n_in,
                              void* d_out, int out_size)
{
    const float* A = nullptr;
    for (int i = 0; i < n_in; i++)
        if (in_sizes[i] == NN * NN) A = (const float*)d_in[i];
    float* out = (float*)d_out;
    topk_tanh_kernel<<<NN, NT>>>(A, out);
}

// round 13
// speedup vs baseline: 1.3951x; 1.0643x over previous
#include <cuda_runtime.h>
#include <stdint.h>

#define NN    8192
#define KSEL  64
#define NT    128          // half-size CTAs: ~12 independent barrier domains / SM
#define EPT4  16           // float4 elements per thread (NN / NT / 4)
#define CAP   512          // candidate capacity (mean ~154, sigma ~12 at th=2.35)
#define THF   2.35f
#define MARGIN_ULPS 8u
#define ONEBITS 0x3f800000u

// Bit-exact replica of XLA's EmitFastTanh (f32, with_fma=true variant).
__device__ __forceinline__ float xla_tanh(float x) {
    const float pc = 7.99881172180175781f;
    float xc = fminf(fmaxf(x, -pc), pc);
    float x2 = __fmul_rn(xc, xc);
    float num = -2.76076847742355e-16f;
    num = __fmaf_rn(x2, num, 2.00018790482477e-13f);
    num = __fmaf_rn(x2, num, -8.60467152213735e-11f);
    num = __fmaf_rn(x2, num, 5.12229709037114e-08f);
    num = __fmaf_rn(x2, num, 1.48572235717979e-05f);
    num = __fmaf_rn(x2, num, 6.37261928875436e-04f);
    num = __fmaf_rn(x2, num, 4.89352455891786e-03f);
    num = __fmul_rn(xc, num);
    float den = 1.19825839466702e-06f;
    den = __fmaf_rn(x2, den, 1.18534705686654e-04f);
    den = __fmaf_rn(x2, den, 2.26843463243900e-03f);
    den = __fmaf_rn(x2, den, 4.89352518554385e-03f);
    float r = __fdiv_rn(num, den);
    return (fabsf(x) < 0.0004f) ? x : r;
}

// packed: (key << 13) | (8191 - idx). Larger packed == better in top_k order.
__device__ __forceinline__ unsigned long long pack_ki(uint32_t key, uint32_t idx) {
    return ((unsigned long long)key << 13) | (8191u - idx);
}

__global__ __launch_bounds__(NT, 12) void topk_tanh_kernel(
    const float* __restrict__ A, float* __restrict__ out)
{
    __shared__ unsigned long long s_pack[CAP];  // raw (A_bits<<32|idx), then packed
    __shared__ float              s_val[CAP];   // signed adj value
    __shared__ uint32_t           s_hist[256];
    __shared__ uint32_t           s_eq[CAP];    // (idx<<9)|slot for boundary-bin ties
    __shared__ uint32_t           s_cnt, s_eqcnt, s_D, s_E;
    __shared__ unsigned long long s_P;

    const int t   = threadIdx.x;
    const int row = blockIdx.x;
    const float* rowA = A + (size_t)row * NN;
    const float4* rp = (const float4*)rowA;
    float4* op = (float4*)(out + (size_t)row * NN);
    float* orow = out + (size_t)row * NN;

    if (t == 0) s_cnt = 0;
    __syncthreads();

    // ---- Phase 1: stream row: |A|-bit candidate filter + fused zero-fill ----
    uint32_t tb = __float_as_uint(THF);
    const float4 z4 = make_float4(0.f, 0.f, 0.f, 0.f);
#pragma unroll
    for (int i = 0; i < EPT4; i++) {
        const int b4 = i * NT + t;
        float4 v = rp[b4];
        op[b4] = z4;                           // zero-fill (selection-independent)
        const uint32_t idx0 = (uint32_t)(b4 * 4);
        uint32_t b0 = __float_as_uint(v.x), b1 = __float_as_uint(v.y);
        uint32_t b2 = __float_as_uint(v.z), b3 = __float_as_uint(v.w);
        if ((b0 & 0x7fffffffu) > tb) { uint32_t p = atomicAdd(&s_cnt, 1u); if (p < CAP) s_pack[p] = ((unsigned long long)b0 << 32) | (idx0 + 0u); }
        if ((b1 & 0x7fffffffu) > tb) { uint32_t p = atomicAdd(&s_cnt, 1u); if (p < CAP) s_pack[p] = ((unsigned long long)b1 << 32) | (idx0 + 1u); }
        if ((b2 & 0x7fffffffu) > tb) { uint32_t p = atomicAdd(&s_cnt, 1u); if (p < CAP) s_pack[p] = ((unsigned long long)b2 << 32) | (idx0 + 2u); }
        if ((b3 & 0x7fffffffu) > tb) { uint32_t p = atomicAdd(&s_cnt, 1u); if (p < CAP) s_pack[p] = ((unsigned long long)b3 << 32) | (idx0 + 3u); }
    }
    __syncthreads();
    uint32_t cnt = s_cnt;

    // ---- Rare: count out of [K, CAP] -> bisect |A|-bit threshold ------------
    if (__builtin_expect(cnt < KSEL || cnt > CAP, 0)) {
        uint32_t lo = 0u, hi = 0x7f800000u;
        if (cnt < KSEL) hi = tb; else lo = tb;
        for (int iter = 0; iter < 34; iter++) {
            uint32_t tk = lo + ((hi - lo) >> 1);
            __syncthreads();
            if (t == 0) s_cnt = 0;
            __syncthreads();
            for (int j = t; j < NN; j += NT) {
                uint32_t b = __float_as_uint(rowA[j]);
                if ((b & 0x7fffffffu) > tk) {
                    uint32_t p = atomicAdd(&s_cnt, 1u);
                    if (p < CAP) s_pack[p] = ((unsigned long long)b << 32) | (uint32_t)j;
                }
            }
            __syncthreads();
            cnt = s_cnt;
            tb = tk;
            if (cnt >= KSEL && cnt <= CAP) break;
            if (cnt < KSEL) hi = tk; else lo = tk;
            if (hi - lo <= 1u) break;
        }
        if (cnt > CAP) cnt = CAP;
    }
    uint32_t c = cnt;

    // ---- Phase 2: exact tanh keys for candidates, in-place repack -----------
    for (uint32_t i = t; i < c; i += NT) {
        unsigned long long raw = s_pack[i];
        float a = __uint_as_float((uint32_t)(raw >> 32));
        uint32_t idx = (uint32_t)(raw & 0xffffffffu);
        float adj = xla_tanh(3.0f * a);
        uint32_t key = __float_as_uint(adj) & 0x7fffffffu;
        s_pack[i] = pack_ki(key, idx);
        s_val[i]  = adj;
    }
    __syncthreads();

    // ---- Phase 3: O(c) histogram select on d = bits(1.0) - key --------------
    const bool selAll = (c < KSEL);
    bool useRank = false;
    if (!selAll) {
        s_hist[t] = 0; s_hist[t + NT] = 0;     // NT == 128, 256 bins
        __syncthreads();
        for (uint32_t i = t; i < c; i += NT) {
            uint32_t d = ONEBITS - (uint32_t)(s_pack[i] >> 13);
            atomicAdd(&s_hist[d > 255u ? 255u : d], 1u);
        }
        __syncthreads();
        if (t < 32) {
            uint32_t p = 0;
#pragma unroll
            for (int j = 0; j < 8; j++) p += s_hist[t * 8 + j];
            uint32_t inc = p;
#pragma unroll
            for (int d = 1; d < 32; d <<= 1) {
                uint32_t v = __shfl_up_sync(0xffffffffu, inc, d);
                if (t >= d) inc += v;
            }
            uint32_t exc = inc - p;
            if (exc < KSEL && inc >= KSEL) {   // exactly one lane
                uint32_t cum = exc;
                for (int j = 0; j < 8; j++) {
                    uint32_t h = s_hist[t * 8 + j];
                    if (cum + h >= KSEL) { s_D = (uint32_t)(t * 8 + j); s_E = KSEL - cum; break; }
                    cum += h;
                }
            }
        }
        __syncthreads();
        if (s_D == 255u) useRank = true;       // overflow bin ambiguous: cold
    }

    // ---- Cold: c^2 rank fallback when histogram can't resolve ---------------
    if (__builtin_expect(useRank, 0)) {
        for (uint32_t i = t; i < c; i += NT) {
            unsigned long long me = s_pack[i];
            uint32_t r = 0;
            for (uint32_t j = 0; j < c; j++) r += (s_pack[j] > me);
            if (r == KSEL - 1) s_P = me;
        }
        __syncthreads();
    }

    // ---- Safety guard: can any excluded element (|A| <= tb) reach Tkey? -----
    if (!selAll) {
        uint32_t Tkey = useRank ? (uint32_t)(s_P >> 13) : (ONEBITS - s_D);
        float tfl = __uint_as_float(tb);
        uint32_t keysafe = (__float_as_uint(xla_tanh(3.0f * tfl)) & 0x7fffffffu) + MARGIN_ULPS;
        if (__builtin_expect(Tkey <= keysafe, 0)) {
            unsigned long long Pcol = ((unsigned long long)Tkey) << 13;
            __syncthreads();
            if (t == 0) s_cnt = 0;
            __syncthreads();
            for (int j = t; j < NN; j += NT) {
                float adj = xla_tanh(3.0f * rowA[j]);
                uint32_t key = __float_as_uint(adj) & 0x7fffffffu;
                unsigned long long pk = pack_ki(key, (uint32_t)j);
                if (pk >= Pcol) {
                    uint32_t p = atomicAdd(&s_cnt, 1u);
                    if (p < CAP) { s_pack[p] = pk; s_val[p] = adj; }
                }
            }
            __syncthreads();
            uint32_t c2 = s_cnt; if (c2 > CAP) c2 = CAP;
            for (uint32_t i = t; i < c2; i += NT) {
                unsigned long long me = s_pack[i];
                uint32_t r = 0;
                for (uint32_t j = 0; j < c2; j++) r += (s_pack[j] > me);
                if (r == KSEL - 1) s_P = me;
            }
            __syncthreads();
            c = c2;
            useRank = true;
        }
    }

    // ---- Phase 4: scatter the exactly-K selected values ---------------------
    if (selAll) {
        for (uint32_t i = t; i < c; i += NT) {
            uint32_t idx = 8191u - (uint32_t)(s_pack[i] & 8191u);
            orow[idx] = s_val[i];
        }
    } else if (useRank) {
        unsigned long long P = s_P;
        for (uint32_t i = t; i < c; i += NT) {
            unsigned long long pk = s_pack[i];
            if (pk >= P) {
                uint32_t idx = 8191u - (uint32_t)(pk & 8191u);
                orow[idx] = s_val[i];
            }
        }
    } else {
        if (t == 0) s_eqcnt = 0;
        __syncthreads();
        const uint32_t D = s_D, E = s_E;
        for (uint32_t i = t; i < c; i += NT) {
            unsigned long long pk = s_pack[i];
            uint32_t d = ONEBITS - (uint32_t)(pk >> 13);
            uint32_t idx = 8191u - (uint32_t)(pk & 8191u);
            if (d < D) {
                orow[idx] = s_val[i];                       // strictly above threshold
            } else if (d == D) {
                uint32_t q = atomicAdd(&s_eqcnt, 1u);
                s_eq[q] = (idx << 9) | i;                   // idx:13b | slot:9b
            }
        }
        __syncthreads();
        const uint32_t Q = s_eqcnt;
        for (uint32_t m = t; m < Q; m += NT) {              // Q^2 ~ 4K: cheap
            uint32_t me = s_eq[m];
            uint32_t r = 0;
            for (uint32_t j = 0; j < Q; j++) r += (s_eq[j] < me);
            if (r < E) {                                    // E lowest indices win
                uint32_t i = me & 511u;
                orow[me >> 9] = s_val[i];
            }
        }
    }
}

extern "C" void kernel_launch(void* const* d_in, const int* in_sizes, int n_in,
                              void* d_out, int out_size)
{
    const float* A = nullptr;
    for (int i = 0; i < n_in; i++)
        if (in_sizes[i] == NN * NN) A = (const float*)d_in[i];
    float* out = (float*)d_out;
    topk_tanh_kernel<<<NN, NT>>>(A, out);
}